// round 14
// baseline (speedup 1.0000x reference)
#include <cuda_runtime.h>
#include <cuda_fp16.h>

#define HW 225
#define ZROW 225          // guaranteed-zero row (all 128 channels zero)
#define NROWS 226
#define NCH 128
// two half activation buffers [226][128]
#define SMEM_BYTES (2*NROWS*NCH*2)

// per-direction tap offsets: d0 horiz, d1 vert, d2 anti-diag, d3 main diag
__constant__ int c_DI0[4] = { 0,-1, 1,-1};
__constant__ int c_DJ0[4] = {-1, 0,-1,-1};
__constant__ int c_DI2[4] = { 0, 1,-1, 1};
__constant__ int c_DJ2[4] = { 1, 0, 1, 1};

// ---- f16 weight arena ----
#define WOFF_DIR 0
#define WOFF_PW  196608
#define WOFF_C1  262144
#define WOFF_C2  278528
#define WOFF_FIN 294912
#define WTOTAL   303104
__device__ __align__(16) __half g_wh[WTOTAL];

__global__ void prep_kernel(const float* __restrict__ rdw,
                            const float* __restrict__ rpw,
                            const float* __restrict__ cw1,
                            const float* __restrict__ cw2,
                            const float* __restrict__ fw) {
    for (int idx = blockIdx.x*blockDim.x + threadIdx.x; idx < WTOTAL;
         idx += gridDim.x*blockDim.x) {
        float v;
        if (idx < WOFF_PW) {
            int c = idx & 127;
            int o = (idx >> 7) & 127;
            int r = idx >> 14;          // i*3 + t
            int t = r % 3;
            int i = r / 3;
            v = rdw[((i*128 + o)*128 + c)*3 + t];
        } else if (idx < WOFF_C1) {
            v = rpw[idx - WOFF_PW];
        } else if (idx < WOFF_C2) {
            v = cw1[idx - WOFF_C1];
        } else if (idx < WOFF_FIN) {
            v = cw2[idx - WOFF_C2];
        } else {
            v = fw[idx - WOFF_FIN];
        }
        g_wh[idx] = __float2half(v);
    }
}

__device__ __forceinline__ float silu_f(float x) {
    return x * (1.0f / (1.0f + __expf(-x)));
}

// half layout [p][c]: row = 256B = 16 granules of 16B (8 halves), granule
// index XOR-swizzled with (p&7).  half index of (p,c):
__device__ __forceinline__ int hidx(int p, int c) {
    return p*128 + ((((c >> 3) ^ (p & 7)) << 3) | (c & 7));
}

__device__ __forceinline__ void mma_16816(float* d,
    unsigned a0, unsigned a1, unsigned a2, unsigned a3,
    unsigned b0, unsigned b1)
{
    asm volatile(
        "mma.sync.aligned.m16n8k16.row.col.f32.f16.f16.f32 "
        "{%0,%1,%2,%3}, {%4,%5,%6,%7}, {%8,%9}, {%0,%1,%2,%3};\n"
        : "+f"(d[0]), "+f"(d[1]), "+f"(d[2]), "+f"(d[3])
        : "r"(a0), "r"(a1), "r"(a2), "r"(a3), "r"(b0), "r"(b1));
}

__device__ __forceinline__ void ldsm_x4(unsigned& r0, unsigned& r1,
                                        unsigned& r2, unsigned& r3,
                                        unsigned addr)
{
    asm volatile(
        "ldmatrix.sync.aligned.m8n8.x4.shared.b16 {%0,%1,%2,%3}, [%4];\n"
        : "=r"(r0), "=r"(r1), "=r"(r2), "=r"(r3) : "r"(addr));
}

// load 16 A-fragment words (2 k-steps x 2 m-tiles) for k-step pair s0, s0+1
__device__ __forceinline__ void loadA(unsigned* a, const unsigned* wt,
                                      int wb0, int s0)
{
#pragma unroll
    for (int s2 = 0; s2 < 2; s2++) {
        int s = s0 + s2;
        unsigned* p = a + 8*s2;
        p[0] = wt[wb0 + 8*s];
        p[1] = wt[wb0 + 512 + 8*s];
        p[2] = wt[wb0 + 8*s + 4];
        p[3] = wt[wb0 + 512 + 8*s + 4];
        p[4] = wt[wb0 + 1024 + 8*s];
        p[5] = wt[wb0 + 1536 + 8*s];
        p[6] = wt[wb0 + 1024 + 8*s + 4];
        p[7] = wt[wb0 + 1536 + 8*s + 4];
    }
}

// swizzle-folded per-lane ldmatrix bases for one tap
__device__ __forceinline__ void calc_axor(unsigned* axor, unsigned sbase,
                                          int pbase, int lr, int di, int dj,
                                          bool shifted)
{
#pragma unroll
    for (int i = 0; i < 8; i++) {
        int p = pbase + i*8 + lr;
        int r = ZROW;
        if (p < HW) {
            if (shifted) {
                int pi = p / 15, pj = p - pi*15;
                if ((unsigned)(pi + di) < 15u && (unsigned)(pj + dj) < 15u)
                    r = p + di*15 + dj;
            } else {
                r = p;
            }
        }
        axor[i] = (sbase + r*256) ^ (unsigned)((r & 7) << 4);
    }
}

// MMA layer, Cin=128 -> Co=128, half activations in smem, weights via LDG.
// 16 warps = 4 out-groups (32 ch = 2 m-tiles) x 4 pos-cols (64 pos = 8 n-tiles).
// A-fragment LDGs are software-pipelined one (tap,sp)-step ahead.
template<int NTAPS, bool ACT, bool RESID>
__device__ __forceinline__ void layer_mma(
    const __half* __restrict__ sin,
    __half* __restrict__ sout,
    const __half* __restrict__ wh,
    const float* __restrict__ bias,
    const __half* __restrict__ sres,
    int di0, int dj0, int di2, int dj2)
{
    const int tid  = threadIdx.x;
    const int wid  = tid >> 5;
    const int lane = tid & 31;
    const int tg = lane >> 2, tk = lane & 3;
    const int lr = lane & 7;        // row-within-tile for ldmatrix
    const int lq = lane >> 3;       // k-granule slot 0..3
    const int oz = wid >> 2, pc = wid & 3;
    const int ob = oz * 32;
    const int pbase = pc * 64;
    const unsigned* w32 = reinterpret_cast<const unsigned*>(wh);
    const int wb0 = (ob + tg)*64 + tk;
    const unsigned sbase = (unsigned)__cvta_generic_to_shared(sin);

    float bl[2], bh[2];
#pragma unroll
    for (int mt = 0; mt < 2; mt++) {
        bl[mt] = bias[ob + mt*16 + tg];
        bh[mt] = bias[ob + mt*16 + tg + 8];
    }

    float acc[2][8][4];
#pragma unroll
    for (int mt = 0; mt < 2; mt++)
#pragma unroll
        for (int i = 0; i < 8; i++)
#pragma unroll
            for (int u = 0; u < 4; u++) acc[mt][i][u] = 0.f;

    unsigned axor[8];
    calc_axor(axor, sbase, pbase, lr, di0, dj0, NTAPS == 3);

    unsigned aAc[16], aAn[16];
    loadA(aAc, w32, wb0, 0);

    const int TS = NTAPS*4;
#pragma unroll 1
    for (int ts = 0; ts < TS; ts++) {
        const int sp = ts & 3;
        // prefetch next step's A fragments (covers L2 latency under MMAs)
        if (ts + 1 < TS)
            loadA(aAn, w32 + ((ts+1) >> 2)*8192, wb0, 2*((ts+1) & 3));

        const unsigned sx = (unsigned)((4*sp + lq) << 4);
#pragma unroll
        for (int i = 0; i < 8; i++) {
            unsigned b0, b1, b2, b3;
            ldsm_x4(b0, b1, b2, b3, axor[i] ^ sx);
            mma_16816(acc[0][i], aAc[0], aAc[1], aAc[2],  aAc[3],  b0, b1);
            mma_16816(acc[1][i], aAc[4], aAc[5], aAc[6],  aAc[7],  b0, b1);
            mma_16816(acc[0][i], aAc[8], aAc[9], aAc[10], aAc[11], b2, b3);
            mma_16816(acc[1][i], aAc[12],aAc[13],aAc[14], aAc[15], b2, b3);
        }

        if (sp == 3 && ts + 1 < TS) {
            int t = (ts + 1) >> 2;
            int di = (t == 0) ? di0 : ((t == 1) ? 0 : di2);
            int dj = (t == 0) ? dj0 : ((t == 1) ? 0 : dj2);
            calc_axor(axor, sbase, pbase, lr, di, dj, NTAPS == 3 && t != 1);
        }
#pragma unroll
        for (int k = 0; k < 16; k++) aAc[k] = aAn[k];
    }

    // epilogue
#pragma unroll
    for (int i = 0; i < 8; i++) {
        int p0 = pbase + i*8 + tk*2;
        int p1 = p0 + 1;
#pragma unroll
        for (int mt = 0; mt < 2; mt++) {
            const int o0 = ob + mt*16 + tg, o1 = o0 + 8;
            float v00 = acc[mt][i][0] + bl[mt];
            float v01 = acc[mt][i][1] + bl[mt];
            float v10 = acc[mt][i][2] + bh[mt];
            float v11 = acc[mt][i][3] + bh[mt];
            if (ACT) {
                v00 = silu_f(v00); v01 = silu_f(v01);
                v10 = silu_f(v10); v11 = silu_f(v11);
            }
            if (p0 < HW) {
                int i00 = hidx(p0, o0), i10 = hidx(p0, o1);
                if (RESID) {
                    v00 += __half2float(sres[i00]);
                    v10 += __half2float(sres[i10]);
                }
                sout[i00] = __float2half(v00);
                sout[i10] = __float2half(v10);
            }
            if (p1 < HW) {
                int i01 = hidx(p1, o0), i11 = hidx(p1, o1);
                if (RESID) {
                    v01 += __half2float(sres[i01]);
                    v11 += __half2float(sres[i11]);
                }
                sout[i01] = __float2half(v01);
                sout[i11] = __float2half(v11);
            }
        }
    }
}

// Final 1x1, 128 -> 64, to global fp32.
// 16 warps = 2 out-groups (32 ch) x 8 pos-cols (32 pos = 4 n-tiles).
__device__ __forceinline__ void final_mma(
    const __half* __restrict__ sin,
    float* __restrict__ gout,
    const __half* __restrict__ wh,
    const float* __restrict__ bias)
{
    const int tid  = threadIdx.x;
    const int wid  = tid >> 5;
    const int lane = tid & 31;
    const int tg = lane >> 2, tk = lane & 3;
    const int lr = lane & 7;
    const int lq = lane >> 3;
    const int oz = wid >> 3, pc = wid & 7;
    const int ob = oz * 32;
    const int pbase = pc * 32;
    const unsigned* w32 = reinterpret_cast<const unsigned*>(wh);
    const int wb0 = (ob + tg)*64 + tk;
    const unsigned sbase = (unsigned)__cvta_generic_to_shared(sin);

    float bl[2], bh[2];
#pragma unroll
    for (int mt = 0; mt < 2; mt++) {
        bl[mt] = bias[ob + mt*16 + tg];
        bh[mt] = bias[ob + mt*16 + tg + 8];
    }

    float acc[2][4][4];
#pragma unroll
    for (int mt = 0; mt < 2; mt++)
#pragma unroll
        for (int i = 0; i < 4; i++)
#pragma unroll
            for (int u = 0; u < 4; u++) acc[mt][i][u] = 0.f;

    unsigned axor[4];
#pragma unroll
    for (int i = 0; i < 4; i++) {
        int p = pbase + i*8 + lr;
        int r = (p < HW) ? p : ZROW;
        axor[i] = (sbase + r*256) ^ (unsigned)((r & 7) << 4);
    }

    unsigned aAc[16], aAn[16];
    loadA(aAc, w32, wb0, 0);

#pragma unroll 1
    for (int sp = 0; sp < 4; sp++) {
        if (sp < 3) loadA(aAn, w32, wb0, 2*(sp + 1));
        const unsigned sx = (unsigned)((4*sp + lq) << 4);
#pragma unroll
        for (int i = 0; i < 4; i++) {
            unsigned b0, b1, b2, b3;
            ldsm_x4(b0, b1, b2, b3, axor[i] ^ sx);
            mma_16816(acc[0][i], aAc[0], aAc[1], aAc[2],  aAc[3],  b0, b1);
            mma_16816(acc[1][i], aAc[4], aAc[5], aAc[6],  aAc[7],  b0, b1);
            mma_16816(acc[0][i], aAc[8], aAc[9], aAc[10], aAc[11], b2, b3);
            mma_16816(acc[1][i], aAc[12],aAc[13],aAc[14], aAc[15], b2, b3);
        }
#pragma unroll
        for (int k = 0; k < 16; k++) aAc[k] = aAn[k];
    }

#pragma unroll
    for (int i = 0; i < 4; i++) {
        int p0 = pbase + i*8 + tk*2;
        int p1 = p0 + 1;
#pragma unroll
        for (int mt = 0; mt < 2; mt++) {
            const int o0 = ob + mt*16 + tg, o1 = o0 + 8;
            if (p0 < HW) {
                gout[o0*HW + p0] = acc[mt][i][0] + bl[mt];
                gout[o1*HW + p0] = acc[mt][i][2] + bh[mt];
            }
            if (p1 < HW) {
                gout[o0*HW + p1] = acc[mt][i][1] + bl[mt];
                gout[o1*HW + p1] = acc[mt][i][3] + bh[mt];
            }
        }
    }
}

__global__ void __launch_bounds__(512, 1)
mix9s_kernel(const float* __restrict__ x,
             const float* __restrict__ dw0, const float* __restrict__ db0,
             const float* __restrict__ rdb, const float* __restrict__ rpb,
             const float* __restrict__ cb1, const float* __restrict__ cb2,
             const float* __restrict__ fb,
             float* __restrict__ out)
{
    extern __shared__ __half smem_h[];
    __half* bufA = smem_h;                      // swizzled half [226][128]
    __half* bufB = smem_h + NROWS*NCH;

    const int tid = threadIdx.x;
    const int b = blockIdx.x & 255;
    const int d = blockIdx.x >> 8;
    const int di0 = c_DI0[d], dj0 = c_DJ0[d], di2 = c_DI2[d], dj2 = c_DJ2[d];

    // zero rows
    if (tid < NCH) {
        bufA[ZROW*NCH + tid] = __float2half(0.f);
        bufB[ZROW*NCH + tid] = __float2half(0.f);
    }
    // stage x fp32 into scratch at start of bufB: xs[c][0..225], slot 225 = 0
    float* xs = reinterpret_cast<float*>(bufB);
    const float* xb = x + b*(2*HW);
    for (int idx = tid; idx < 2*HW; idx += 512) {
        int c = idx / HW;
        int p = idx - c*HW;
        xs[c*NROWS + p] = xb[idx];
    }
    if (tid < 2) xs[tid*NROWS + HW] = 0.f;
    __syncthreads();

    // ---- dconv0: Cin=2, 3 taps, silu -> bufA (scalar) ----
    {
        const int oz = tid >> 4, pl = tid & 15;   // 32 groups x 4 outputs
        const int ob = oz * 4;
        float wr_[4][2][3];
#pragma unroll
        for (int u = 0; u < 4; u++)
#pragma unroll
            for (int c = 0; c < 2; c++)
#pragma unroll
                for (int t = 0; t < 3; t++)
                    wr_[u][c][t] = dw0[((ob+u)*2 + c)*3 + t];
        float bb[4];
#pragma unroll
        for (int u = 0; u < 4; u++) bb[u] = db0[ob+u];

        const int d0 = di0*15 + dj0;
        const int d2 = di2*15 + dj2;
#pragma unroll 1
        for (int ch = 0; ch < 4; ch++) {
#pragma unroll
            for (int j = 0; j < 4; j++) {
                int p = pl + 16*(ch*4 + j);
                bool v = p < HW;
                int rv = v ? p : HW;
                int r0 = HW, r2 = HW;
                int pi = p / 15, pj = p - pi*15;
                if (v && (unsigned)(pi+di0) < 15u && (unsigned)(pj+dj0) < 15u)
                    r0 = p + d0;
                if (v && (unsigned)(pi+di2) < 15u && (unsigned)(pj+dj2) < 15u)
                    r2 = p + d2;

                float v0[2], vc[2], v2[2];
#pragma unroll
                for (int c = 0; c < 2; c++) {
                    v0[c] = xs[c*NROWS + r0];
                    vc[c] = xs[c*NROWS + rv];
                    v2[c] = xs[c*NROWS + r2];
                }
                if (v) {
#pragma unroll
                    for (int u = 0; u < 4; u++) {
                        float a = bb[u];
#pragma unroll
                        for (int c = 0; c < 2; c++) {
                            a = fmaf(wr_[u][c][0], v0[c], a);
                            a = fmaf(wr_[u][c][1], vc[c], a);
                            a = fmaf(wr_[u][c][2], v2[c], a);
                        }
                        bufA[hidx(rv, ob+u)] = __float2half(silu_f(a));
                    }
                }
            }
        }
    }
    __syncthreads();

    // ---- 4 directional res blocks ----
#pragma unroll 1
    for (int i = 0; i < 4; i++) {
        layer_mma<3, true, false>(bufA, bufB,
            g_wh + WOFF_DIR + i*3*16384, rdb + i*128, nullptr,
            di0, dj0, di2, dj2);
        __syncthreads();
        layer_mma<1, true, true>(bufB, bufA,
            g_wh + WOFF_PW + i*16384, rpb + i*128, bufA, 0, 0, 0, 0);
        __syncthreads();
    }

    // ---- Conv0d res block ----
    layer_mma<1, true, false>(bufA, bufB, g_wh + WOFF_C1, cb1, nullptr, 0,0,0,0);
    __syncthreads();
    layer_mma<1, true, true>(bufB, bufA, g_wh + WOFF_C2, cb2, bufA, 0,0,0,0);
    __syncthreads();

    // ---- final 1x1 (128 -> 64) straight to global ----
    final_mma(bufA, out + (b*4 + d)*64*HW, g_wh + WOFF_FIN, fb);
}

extern "C" void kernel_launch(void* const* d_in, const int* in_sizes, int n_in,
                              void* d_out, int out_size) {
    (void)in_sizes; (void)n_in; (void)out_size;
    const float* x   = (const float*)d_in[0];
    const float* dw0 = (const float*)d_in[1];
    const float* db0 = (const float*)d_in[2];
    const float* rdw = (const float*)d_in[3];
    const float* rdb = (const float*)d_in[4];
    const float* rpw = (const float*)d_in[5];
    const float* rpb = (const float*)d_in[6];
    const float* cw1 = (const float*)d_in[7];
    const float* cb1 = (const float*)d_in[8];
    const float* cw2 = (const float*)d_in[9];
    const float* cb2 = (const float*)d_in[10];
    const float* fw  = (const float*)d_in[11];
    const float* fb  = (const float*)d_in[12];
    float* out = (float*)d_out;

    cudaFuncSetAttribute(mix9s_kernel,
                         cudaFuncAttributeMaxDynamicSharedMemorySize, SMEM_BYTES);

    prep_kernel<<<296, 1024>>>(rdw, rpw, cw1, cw2, fw);
    mix9s_kernel<<<1024, 512, SMEM_BYTES>>>(
        x, dw0, db0, rdb, rpb, cb1, cb2, fb, out);
}

// round 15
// speedup vs baseline: 1.1428x; 1.1428x over previous
#include <cuda_runtime.h>
#include <cuda_fp16.h>

#define HW 225
#define ZROW 225          // guaranteed-zero row (all 128 channels zero)
#define NROWS 226
#define NCH 128
// two half activation buffers [226][128] = 113 KB -> 2 CTAs/SM co-resident
#define SMEM_BYTES (2*NROWS*NCH*2)

// per-direction tap offsets: d0 horiz, d1 vert, d2 anti-diag, d3 main diag
__constant__ int c_DI0[4] = { 0,-1, 1,-1};
__constant__ int c_DJ0[4] = {-1, 0,-1,-1};
__constant__ int c_DI2[4] = { 0, 1,-1, 1};
__constant__ int c_DJ2[4] = { 1, 0, 1, 1};

// ---- f16 weight arena ----
#define WOFF_DIR 0
#define WOFF_PW  196608
#define WOFF_C1  262144
#define WOFF_C2  278528
#define WOFF_FIN 294912
#define WTOTAL   303104
__device__ __align__(16) __half g_wh[WTOTAL];

__global__ void prep_kernel(const float* __restrict__ rdw,
                            const float* __restrict__ rpw,
                            const float* __restrict__ cw1,
                            const float* __restrict__ cw2,
                            const float* __restrict__ fw) {
    for (int idx = blockIdx.x*blockDim.x + threadIdx.x; idx < WTOTAL;
         idx += gridDim.x*blockDim.x) {
        float v;
        if (idx < WOFF_PW) {
            int c = idx & 127;
            int o = (idx >> 7) & 127;
            int r = idx >> 14;          // i*3 + t
            int t = r % 3;
            int i = r / 3;
            v = rdw[((i*128 + o)*128 + c)*3 + t];
        } else if (idx < WOFF_C1) {
            v = rpw[idx - WOFF_PW];
        } else if (idx < WOFF_C2) {
            v = cw1[idx - WOFF_C1];
        } else if (idx < WOFF_FIN) {
            v = cw2[idx - WOFF_C2];
        } else {
            v = fw[idx - WOFF_FIN];
        }
        g_wh[idx] = __float2half(v);
    }
}

__device__ __forceinline__ float silu_f(float x) {
    return x * (1.0f / (1.0f + __expf(-x)));
}

// half layout [p][c]: row = 256B = 16 granules of 16B (8 halves), granule
// index XOR-swizzled with (p&7).  half index of (p,c):
__device__ __forceinline__ int hidx(int p, int c) {
    return p*128 + ((((c >> 3) ^ (p & 7)) << 3) | (c & 7));
}

__device__ __forceinline__ void mma_16816(float* d,
    unsigned a0, unsigned a1, unsigned a2, unsigned a3,
    unsigned b0, unsigned b1)
{
    asm volatile(
        "mma.sync.aligned.m16n8k16.row.col.f32.f16.f16.f32 "
        "{%0,%1,%2,%3}, {%4,%5,%6,%7}, {%8,%9}, {%0,%1,%2,%3};\n"
        : "+f"(d[0]), "+f"(d[1]), "+f"(d[2]), "+f"(d[3])
        : "r"(a0), "r"(a1), "r"(a2), "r"(a3), "r"(b0), "r"(b1));
}

__device__ __forceinline__ void ldsm_x4(unsigned& r0, unsigned& r1,
                                        unsigned& r2, unsigned& r3,
                                        unsigned addr)
{
    asm volatile(
        "ldmatrix.sync.aligned.m8n8.x4.shared.b16 {%0,%1,%2,%3}, [%4];\n"
        : "=r"(r0), "=r"(r1), "=r"(r2), "=r"(r3) : "r"(addr));
}

// MMA layer, Cin=128 -> Co=128, half activations in smem (R9 inner loop).
// 8 warps = 4 out-groups (32 ch = 2 m-tiles) x 2 pos-col-pairs; q-loop covers
// the two 64-pos halves of each pair sequentially.
template<int NTAPS, bool ACT, bool RESID>
__device__ __forceinline__ void layer_mma(
    const __half* __restrict__ sin,
    __half* __restrict__ sout,
    const __half* __restrict__ wh,
    const float* __restrict__ bias,
    const __half* __restrict__ sres,
    int di0, int dj0, int di2, int dj2)
{
    const int tid  = threadIdx.x;
    const int wid  = tid >> 5;
    const int lane = tid & 31;
    const int tg = lane >> 2, tk = lane & 3;
    const int lr = lane & 7;        // row-within-tile for ldmatrix
    const int lq = lane >> 3;       // k-granule slot 0..3
    const int oz = wid >> 1, pc2 = wid & 1;
    const int ob = oz * 32;
    const unsigned* w32 = reinterpret_cast<const unsigned*>(wh);
    const int wb0 = (ob + tg)*64 + tk;
    const unsigned sbase = (unsigned)__cvta_generic_to_shared(sin);

    float bl[2], bh[2];
#pragma unroll
    for (int mt = 0; mt < 2; mt++) {
        bl[mt] = bias[ob + mt*16 + tg];
        bh[mt] = bias[ob + mt*16 + tg + 8];
    }

#pragma unroll 1
    for (int q = 0; q < 2; q++) {
        const int pbase = pc2*128 + q*64;

        float acc[2][8][4];
#pragma unroll
        for (int mt = 0; mt < 2; mt++)
#pragma unroll
            for (int i = 0; i < 8; i++)
#pragma unroll
                for (int u = 0; u < 4; u++) acc[mt][i][u] = 0.f;

#pragma unroll 1
        for (int tap = 0; tap < NTAPS; tap++) {
            int di = 0, dj = 0;
            if (NTAPS == 3) {
                di = (tap == 0) ? di0 : ((tap == 1) ? 0 : di2);
                dj = (tap == 0) ? dj0 : ((tap == 1) ? 0 : dj2);
            }
            // per-lane swizzle-folded ldmatrix base for each n-tile
            unsigned axor[8];
#pragma unroll
            for (int i = 0; i < 8; i++) {
                int p = pbase + i*8 + lr;
                int r = ZROW;
                if (p < HW) {
                    if (NTAPS == 3 && tap != 1) {
                        int pi = p / 15, pj = p - pi*15;
                        if ((unsigned)(pi + di) < 15u && (unsigned)(pj + dj) < 15u)
                            r = p + di*15 + dj;
                    } else {
                        r = p;
                    }
                }
                axor[i] = (sbase + r*256) ^ (unsigned)((r & 7) << 4);
            }
            const unsigned* wt = w32 + tap*8192;

#pragma unroll 1
            for (int sp = 0; sp < 4; sp++) {
                unsigned aA[2][8];
#pragma unroll
                for (int s2 = 0; s2 < 2; s2++) {
                    int s = 2*sp + s2;
                    aA[s2][0] = wt[wb0 + 8*s];
                    aA[s2][1] = wt[wb0 + 512 + 8*s];
                    aA[s2][2] = wt[wb0 + 8*s + 4];
                    aA[s2][3] = wt[wb0 + 512 + 8*s + 4];
                    aA[s2][4] = wt[wb0 + 1024 + 8*s];
                    aA[s2][5] = wt[wb0 + 1536 + 8*s];
                    aA[s2][6] = wt[wb0 + 1024 + 8*s + 4];
                    aA[s2][7] = wt[wb0 + 1536 + 8*s + 4];
                }
                const unsigned sx = (unsigned)((4*sp + lq) << 4);
#pragma unroll
                for (int i = 0; i < 8; i++) {
                    unsigned b0, b1, b2, b3;
                    ldsm_x4(b0, b1, b2, b3, axor[i] ^ sx);
                    mma_16816(acc[0][i], aA[0][0], aA[0][1], aA[0][2], aA[0][3], b0, b1);
                    mma_16816(acc[1][i], aA[0][4], aA[0][5], aA[0][6], aA[0][7], b0, b1);
                    mma_16816(acc[0][i], aA[1][0], aA[1][1], aA[1][2], aA[1][3], b2, b3);
                    mma_16816(acc[1][i], aA[1][4], aA[1][5], aA[1][6], aA[1][7], b2, b3);
                }
            }
        }

        // epilogue for this q
#pragma unroll
        for (int i = 0; i < 8; i++) {
            int p0 = pbase + i*8 + tk*2;
            int p1 = p0 + 1;
#pragma unroll
            for (int mt = 0; mt < 2; mt++) {
                const int o0 = ob + mt*16 + tg, o1 = o0 + 8;
                float v00 = acc[mt][i][0] + bl[mt];
                float v01 = acc[mt][i][1] + bl[mt];
                float v10 = acc[mt][i][2] + bh[mt];
                float v11 = acc[mt][i][3] + bh[mt];
                if (ACT) {
                    v00 = silu_f(v00); v01 = silu_f(v01);
                    v10 = silu_f(v10); v11 = silu_f(v11);
                }
                if (p0 < HW) {
                    int i00 = hidx(p0, o0), i10 = hidx(p0, o1);
                    if (RESID) {
                        v00 += __half2float(sres[i00]);
                        v10 += __half2float(sres[i10]);
                    }
                    sout[i00] = __float2half(v00);
                    sout[i10] = __float2half(v10);
                }
                if (p1 < HW) {
                    int i01 = hidx(p1, o0), i11 = hidx(p1, o1);
                    if (RESID) {
                        v01 += __half2float(sres[i01]);
                        v11 += __half2float(sres[i11]);
                    }
                    sout[i01] = __float2half(v01);
                    sout[i11] = __float2half(v11);
                }
            }
        }
    }
}

// Final 1x1, 128 -> 64, to global fp32.
// 8 warps = 2 out-groups (32 ch) x 4 pos-cols (64 pos = 8 n-tiles).
__device__ __forceinline__ void final_mma(
    const __half* __restrict__ sin,
    float* __restrict__ gout,
    const __half* __restrict__ wh,
    const float* __restrict__ bias)
{
    const int tid  = threadIdx.x;
    const int wid  = tid >> 5;
    const int lane = tid & 31;
    const int tg = lane >> 2, tk = lane & 3;
    const int lr = lane & 7;
    const int lq = lane >> 3;
    const int oz = wid >> 2, pc = wid & 3;
    const int ob = oz * 32;
    const int pbase = pc * 64;
    const unsigned* w32 = reinterpret_cast<const unsigned*>(wh);
    const int wb0 = (ob + tg)*64 + tk;
    const unsigned sbase = (unsigned)__cvta_generic_to_shared(sin);

    float bl[2], bh[2];
#pragma unroll
    for (int mt = 0; mt < 2; mt++) {
        bl[mt] = bias[ob + mt*16 + tg];
        bh[mt] = bias[ob + mt*16 + tg + 8];
    }

    float acc[2][8][4];
#pragma unroll
    for (int mt = 0; mt < 2; mt++)
#pragma unroll
        for (int i = 0; i < 8; i++)
#pragma unroll
            for (int u = 0; u < 4; u++) acc[mt][i][u] = 0.f;

    unsigned axor[8];
#pragma unroll
    for (int i = 0; i < 8; i++) {
        int p = pbase + i*8 + lr;
        int r = (p < HW) ? p : ZROW;
        axor[i] = (sbase + r*256) ^ (unsigned)((r & 7) << 4);
    }

#pragma unroll 1
    for (int sp = 0; sp < 4; sp++) {
        unsigned aA[2][8];
#pragma unroll
        for (int s2 = 0; s2 < 2; s2++) {
            int s = 2*sp + s2;
            aA[s2][0] = w32[wb0 + 8*s];
            aA[s2][1] = w32[wb0 + 512 + 8*s];
            aA[s2][2] = w32[wb0 + 8*s + 4];
            aA[s2][3] = w32[wb0 + 512 + 8*s + 4];
            aA[s2][4] = w32[wb0 + 1024 + 8*s];
            aA[s2][5] = w32[wb0 + 1536 + 8*s];
            aA[s2][6] = w32[wb0 + 1024 + 8*s + 4];
            aA[s2][7] = w32[wb0 + 1536 + 8*s + 4];
        }
        const unsigned sx = (unsigned)((4*sp + lq) << 4);
#pragma unroll
        for (int i = 0; i < 8; i++) {
            unsigned b0, b1, b2, b3;
            ldsm_x4(b0, b1, b2, b3, axor[i] ^ sx);
            mma_16816(acc[0][i], aA[0][0], aA[0][1], aA[0][2], aA[0][3], b0, b1);
            mma_16816(acc[1][i], aA[0][4], aA[0][5], aA[0][6], aA[0][7], b0, b1);
            mma_16816(acc[0][i], aA[1][0], aA[1][1], aA[1][2], aA[1][3], b2, b3);
            mma_16816(acc[1][i], aA[1][4], aA[1][5], aA[1][6], aA[1][7], b2, b3);
        }
    }

#pragma unroll
    for (int i = 0; i < 8; i++) {
        int p0 = pbase + i*8 + tk*2;
        int p1 = p0 + 1;
#pragma unroll
        for (int mt = 0; mt < 2; mt++) {
            const int o0 = ob + mt*16 + tg, o1 = o0 + 8;
            if (p0 < HW) {
                gout[o0*HW + p0] = acc[mt][i][0] + bl[mt];
                gout[o1*HW + p0] = acc[mt][i][2] + bh[mt];
            }
            if (p1 < HW) {
                gout[o0*HW + p1] = acc[mt][i][1] + bl[mt];
                gout[o1*HW + p1] = acc[mt][i][3] + bh[mt];
            }
        }
    }
}

__global__ void __launch_bounds__(256, 2)
mix9s_kernel(const float* __restrict__ x,
             const float* __restrict__ dw0, const float* __restrict__ db0,
             const float* __restrict__ rdb, const float* __restrict__ rpb,
             const float* __restrict__ cb1, const float* __restrict__ cb2,
             const float* __restrict__ fb,
             float* __restrict__ out)
{
    extern __shared__ __half smem_h[];
    __half* bufA = smem_h;                      // swizzled half [226][128]
    __half* bufB = smem_h + NROWS*NCH;

    const int tid = threadIdx.x;
    const int b = blockIdx.x & 255;
    const int d = blockIdx.x >> 8;
    const int di0 = c_DI0[d], dj0 = c_DJ0[d], di2 = c_DI2[d], dj2 = c_DJ2[d];

    // zero rows
    if (tid < NCH) {
        bufA[ZROW*NCH + tid] = __float2half(0.f);
        bufB[ZROW*NCH + tid] = __float2half(0.f);
    }
    // stage x fp32 into scratch at start of bufB: xs[c][0..225], slot 225 = 0
    float* xs = reinterpret_cast<float*>(bufB);
    const float* xb = x + b*(2*HW);
    for (int idx = tid; idx < 2*HW; idx += 256) {
        int c = idx / HW;
        int p = idx - c*HW;
        xs[c*NROWS + p] = xb[idx];
    }
    if (tid < 2) xs[tid*NROWS + HW] = 0.f;
    __syncthreads();

    // ---- dconv0: Cin=2, 3 taps, silu -> bufA (scalar) ----
    {
        const int oz = tid >> 4, pl = tid & 15;   // 16 groups x 8 outputs
        const int ob = oz * 8;
        float wr_[8][2][3];
#pragma unroll
        for (int u = 0; u < 8; u++)
#pragma unroll
            for (int c = 0; c < 2; c++)
#pragma unroll
                for (int t = 0; t < 3; t++)
                    wr_[u][c][t] = dw0[((ob+u)*2 + c)*3 + t];
        float bb[8];
#pragma unroll
        for (int u = 0; u < 8; u++) bb[u] = db0[ob+u];

        const int d0 = di0*15 + dj0;
        const int d2 = di2*15 + dj2;
#pragma unroll 1
        for (int ch = 0; ch < 4; ch++) {
#pragma unroll
            for (int j = 0; j < 4; j++) {
                int p = pl + 16*(ch*4 + j);
                bool v = p < HW;
                int rv = v ? p : HW;
                int r0 = HW, r2 = HW;
                int pi = p / 15, pj = p - pi*15;
                if (v && (unsigned)(pi+di0) < 15u && (unsigned)(pj+dj0) < 15u)
                    r0 = p + d0;
                if (v && (unsigned)(pi+di2) < 15u && (unsigned)(pj+dj2) < 15u)
                    r2 = p + d2;

                float v0[2], vc[2], v2[2];
#pragma unroll
                for (int c = 0; c < 2; c++) {
                    v0[c] = xs[c*NROWS + r0];
                    vc[c] = xs[c*NROWS + rv];
                    v2[c] = xs[c*NROWS + r2];
                }
                if (v) {
#pragma unroll
                    for (int u = 0; u < 8; u++) {
                        float a = bb[u];
#pragma unroll
                        for (int c = 0; c < 2; c++) {
                            a = fmaf(wr_[u][c][0], v0[c], a);
                            a = fmaf(wr_[u][c][1], vc[c], a);
                            a = fmaf(wr_[u][c][2], v2[c], a);
                        }
                        bufA[hidx(rv, ob+u)] = __float2half(silu_f(a));
                    }
                }
            }
        }
    }
    __syncthreads();

    // ---- 4 directional res blocks ----
#pragma unroll 1
    for (int i = 0; i < 4; i++) {
        layer_mma<3, true, false>(bufA, bufB,
            g_wh + WOFF_DIR + i*3*16384, rdb + i*128, nullptr,
            di0, dj0, di2, dj2);
        __syncthreads();
        layer_mma<1, true, true>(bufB, bufA,
            g_wh + WOFF_PW + i*16384, rpb + i*128, bufA, 0, 0, 0, 0);
        __syncthreads();
    }

    // ---- Conv0d res block ----
    layer_mma<1, true, false>(bufA, bufB, g_wh + WOFF_C1, cb1, nullptr, 0,0,0,0);
    __syncthreads();
    layer_mma<1, true, true>(bufB, bufA, g_wh + WOFF_C2, cb2, bufA, 0,0,0,0);
    __syncthreads();

    // ---- final 1x1 (128 -> 64) straight to global ----
    final_mma(bufA, out + (b*4 + d)*64*HW, g_wh + WOFF_FIN, fb);
}

extern "C" void kernel_launch(void* const* d_in, const int* in_sizes, int n_in,
                              void* d_out, int out_size) {
    (void)in_sizes; (void)n_in; (void)out_size;
    const float* x   = (const float*)d_in[0];
    const float* dw0 = (const float*)d_in[1];
    const float* db0 = (const float*)d_in[2];
    const float* rdw = (const float*)d_in[3];
    const float* rdb = (const float*)d_in[4];
    const float* rpw = (const float*)d_in[5];
    const float* rpb = (const float*)d_in[6];
    const float* cw1 = (const float*)d_in[7];
    const float* cb1 = (const float*)d_in[8];
    const float* cw2 = (const float*)d_in[9];
    const float* cb2 = (const float*)d_in[10];
    const float* fw  = (const float*)d_in[11];
    const float* fb  = (const float*)d_in[12];
    float* out = (float*)d_out;

    cudaFuncSetAttribute(mix9s_kernel,
                         cudaFuncAttributeMaxDynamicSharedMemorySize, SMEM_BYTES);

    prep_kernel<<<296, 1024>>>(rdw, rpw, cw1, cw2, fw);
    mix9s_kernel<<<1024, 256, SMEM_BYTES>>>(
        x, dw0, db0, rdb, rpb, cb1, cb2, fb, out);
}